// round 9
// baseline (speedup 1.0000x reference)
#include <cuda_runtime.h>
typedef unsigned long long u64;

#define TT 2048
#define BB 4096
#define OUTLEN 25
#define TPW 20             // batches per warp: 10 pairs x 2 packed
#define WPD 205            // warps per direction
#define NWIN (TT/8)        // 256 windows of 8 steps

__device__ float g_y[BB * 18];

__device__ __forceinline__ u64 pack2(float lo, float hi) {
    u64 d; asm("mov.b64 %0,{%1,%2};" : "=l"(d) : "f"(lo), "f"(hi)); return d;
}
__device__ __forceinline__ void unpack2(u64 v, float& lo, float& hi) {
    asm("mov.b64 {%0,%1},%2;" : "=f"(lo), "=f"(hi) : "l"(v));
}
__device__ __forceinline__ u64 fma2(u64 a, u64 b, u64 c) {
    u64 d; asm("fma.rn.f32x2 %0,%1,%2,%3;" : "=l"(d) : "l"(a), "l"(b), "l"(c)); return d;
}
__device__ __forceinline__ u64 mul2(u64 a, u64 b) {
    u64 d; asm("mul.rn.f32x2 %0,%1,%2;" : "=l"(d) : "l"(a), "l"(b)); return d;
}
__device__ __forceinline__ u64 add2(u64 a, u64 b) {
    u64 d; asm("add.rn.f32x2 %0,%1,%2;" : "=l"(d) : "l"(a), "l"(b)); return d;
}
__device__ __forceinline__ float tanha(float x) {
    float y; asm("tanh.approx.f32 %0,%1;" : "=f"(y) : "f"(x)); return y;
}
__device__ __forceinline__ float ftanh(float x) {
    x = fminf(fmaxf(x, -9.0f), 9.0f);
    float e = __expf(2.0f * x);
    return __fdividef(e - 1.0f, e + 1.0f);
}

__global__ void dummy_kernel() {}

// ---------------------------------------------------------------------------
// Stage 1: bidirectional Elman RNN H1=9 over T=2048, f32x2-packed.
// Warp = 10 lane-triples x 2 batches (lo/hi of f32x2). Lane r of a triple
// owns units 3r..3r+2 of both batches. 103 CTAs x 4 warps = 1 warp/SMSP.
// x is PRE-PACKED by the loader into per-warp smem as (A,B) u64 values,
// layout [pair][step q][k padded to 6] -> consumer does 2xLDS.128 + LDS.64
// per step and ZERO pack instructions. Double-buffered via LDG prefetch regs.
// zx folded into the recurrent fma chains (no separate add tree).
// tanh.approx except the last 32 steps (precise tail; contraction wipes the
// approx error - verified R0/R5/R6/R8: rel_err pinned at 1.7e-7).
// ---------------------------------------------------------------------------
__global__ __launch_bounds__(128, 1) void rnn1_kernel(
    const float* __restrict__ x,
    const float* __restrict__ wih_f, const float* __restrict__ whh_f,
    const float* __restrict__ bih_f, const float* __restrict__ bhh_f,
    const float* __restrict__ wih_b, const float* __restrict__ whh_b,
    const float* __restrict__ bih_b, const float* __restrict__ bhh_b)
{
    // [warp][buf][pair*48 + q*6 + k] u64 (k 0..4 used, 5 = pad)
    __shared__ u64 sxu[4][2][480];

    const int wIn  = threadIdx.x >> 5;
    const int lane = threadIdx.x & 31;
    const int wid  = blockIdx.x * 4 + wIn;
    if (wid >= 2 * WPD) return;

    const bool bwd = (wid >= WPD);
    const int  wg  = bwd ? wid - WPD : wid;
    const int  tri = min(lane / 3, 9);     // lanes 30,31 shadow pair 9
    const int  r   = lane % 3;
    const int  rA  = (r + 1) % 3, rB = (r + 2) % 3;
    const int  laneA = 3 * tri + rA, laneB = 3 * tri + rB;

    const float* wih = bwd ? wih_b : wih_f;
    const float* whh = bwd ? whh_b : whh_f;
    const float* bih = bwd ? bih_b : bih_f;
    const float* bhh = bwd ? bhh_b : bhh_f;

    // packed weights (same value both halves; both batches share direction)
    u64 WX[3][5], WhO[3][3], WhA[3][3], WhB[3][3], B2[3];
    #pragma unroll
    for (int m = 0; m < 3; m++) {
        const int j = 3 * r + m;
        #pragma unroll
        for (int k = 0; k < 5; k++) { float w = wih[j*5+k]; WX[m][k] = pack2(w, w); }
        #pragma unroll
        for (int i = 0; i < 3; i++) {
            float wo = whh[j*9 + 3*r  + i]; WhO[m][i] = pack2(wo, wo);
            float wa = whh[j*9 + 3*rA + i]; WhA[m][i] = pack2(wa, wa);
            float wb = whh[j*9 + 3*rB + i]; WhB[m][i] = pack2(wb, wb);
        }
        float bv = bih[j] + bhh[j];
        B2[m] = pack2(bv, bv);
    }

    // ---- loader: 100 chunks (pair p 0..9, chunk c 0..9). Chunk c = float4
    // covering window-flat floats 4c..4c+3 (flat = q*5+k). Lane handles
    // chunks lane, lane+32, lane+64 (+96 for lanes 0..3): LDG.128 from
    // batch 2p (A) and 2p+1 (B), packs 4 u64s, STS.64 to [p*48 + q*6 + k].
    const char* xc = (const char*)x;
    size_t   gA[4], gB[4];
    unsigned dstix[4][4];
    #pragma unroll
    for (int kk = 0; kk < 4; kk++) {
        int idc = min(lane + 32 * kk, 99);
        int p = idc / 10, c = idc - 10 * p;
        int ba = min(wg * TPW + 2 * p, BB - 1);
        int bb = min(ba + 1, BB - 1);
        gA[kk] = (size_t)ba * (TT * 20) + (size_t)c * 16;
        gB[kk] = (size_t)bb * (TT * 20) + (size_t)c * 16;
        #pragma unroll
        for (int u = 0; u < 4; u++) {
            int flat = 4 * c + u;
            int q = flat / 5, k = flat - 5 * q;
            dstix[kk][u] = (unsigned)(p * 48 + q * 6 + k);
        }
    }
    float4 pfA[4], pfB[4];

    #define PFLOAD(g) do {                                                    \
        size_t wb = (size_t)(bwd ? (TT - 8 - 8 * (g)) : (8 * (g))) * 20;      \
        _Pragma("unroll")                                                     \
        for (int kk = 0; kk < 4; kk++)                                        \
            if (lane + 32 * kk < 100) {                                       \
                pfA[kk] = *reinterpret_cast<const float4*>(xc + gA[kk] + wb); \
                pfB[kk] = *reinterpret_cast<const float4*>(xc + gB[kk] + wb); \
            }                                                                 \
    } while (0)

    #define STSW(buf) do {                                                    \
        u64* s = &sxu[wIn][buf][0];                                           \
        _Pragma("unroll")                                                     \
        for (int kk = 0; kk < 4; kk++)                                        \
            if (lane + 32 * kk < 100) {                                       \
                s[dstix[kk][0]] = pack2(pfA[kk].x, pfB[kk].x);                \
                s[dstix[kk][1]] = pack2(pfA[kk].y, pfB[kk].y);                \
                s[dstix[kk][2]] = pack2(pfA[kk].z, pfB[kk].z);                \
                s[dstix[kk][3]] = pack2(pfA[kk].w, pfB[kk].w);                \
            }                                                                 \
    } while (0)

    u64 hP[3] = {0, 0, 0}, Ha[3] = {0, 0, 0}, Hb[3] = {0, 0, 0};
    u64 zxw[4][3];

    // bulk x-projection for a 4-step half-window: pre-packed u64 reads,
    // no pack instructions.
    #define ZXH(buf, half) do {                                               \
        const u64* xs = &sxu[wIn][buf][tri * 48 + (half) * 24];               \
        _Pragma("unroll")                                                     \
        for (int q = 0; q < 4; q++) {                                         \
            ulonglong2 v01 = *reinterpret_cast<const ulonglong2*>(xs + q*6);  \
            ulonglong2 v23 = *reinterpret_cast<const ulonglong2*>(xs + q*6+2);\
            u64 X4 = xs[q*6+4];                                               \
            _Pragma("unroll")                                                 \
            for (int m = 0; m < 3; m++) {                                     \
                u64 z = fma2(WX[m][0], v01.x, B2[m]);                         \
                z = fma2(WX[m][1], v01.y, z); z = fma2(WX[m][2], v23.x, z);   \
                z = fma2(WX[m][3], v23.y, z); z = fma2(WX[m][4], X4, z);      \
                zxw[q][m] = z;                                                \
            }                                                                 \
        }                                                                     \
    } while (0)

    // recurrent step: zx folded into the t1 chain (own h first - issues in
    // the shfl shadow - then Ha), Hb on a short side chain, single add2.
    #define STEP(TANHF, q) do {                                               \
        u64 nh[3];                                                            \
        _Pragma("unroll")                                                     \
        for (int m = 0; m < 3; m++) {                                         \
            u64 t1 = fma2(WhO[m][0], hP[0], zxw[q][m]);                       \
            t1 = fma2(WhO[m][1], hP[1], t1);                                  \
            t1 = fma2(WhO[m][2], hP[2], t1);                                  \
            t1 = fma2(WhA[m][0], Ha[0], t1);                                  \
            t1 = fma2(WhA[m][1], Ha[1], t1);                                  \
            t1 = fma2(WhA[m][2], Ha[2], t1);                                  \
            u64 t2 = mul2(WhB[m][0], Hb[0]);                                  \
            t2 = fma2(WhB[m][1], Hb[1], t2);                                  \
            t2 = fma2(WhB[m][2], Hb[2], t2);                                  \
            u64 z = add2(t1, t2);                                             \
            float sa, sb; unpack2(z, sa, sb);                                 \
            nh[m] = pack2(TANHF(sa), TANHF(sb));                              \
        }                                                                     \
        hP[0] = nh[0]; hP[1] = nh[1]; hP[2] = nh[2];                          \
        Ha[0] = __shfl_sync(0xffffffffu, hP[0], laneA);                       \
        Ha[1] = __shfl_sync(0xffffffffu, hP[1], laneA);                       \
        Ha[2] = __shfl_sync(0xffffffffu, hP[2], laneA);                       \
        Hb[0] = __shfl_sync(0xffffffffu, hP[0], laneB);                       \
        Hb[1] = __shfl_sync(0xffffffffu, hP[1], laneB);                       \
        Hb[2] = __shfl_sync(0xffffffffu, hP[2], laneB);                       \
    } while (0)

    #define CONS(TANHF, buf) do {                                             \
        if (!bwd) {                                                           \
            ZXH(buf, 0);                                                      \
            STEP(TANHF, 0); STEP(TANHF, 1); STEP(TANHF, 2); STEP(TANHF, 3);   \
            ZXH(buf, 1);                                                      \
            STEP(TANHF, 0); STEP(TANHF, 1); STEP(TANHF, 2); STEP(TANHF, 3);   \
        } else {                                                              \
            ZXH(buf, 1);                                                      \
            STEP(TANHF, 3); STEP(TANHF, 2); STEP(TANHF, 1); STEP(TANHF, 0);   \
            ZXH(buf, 0);                                                      \
            STEP(TANHF, 3); STEP(TANHF, 2); STEP(TANHF, 1); STEP(TANHF, 0);   \
        }                                                                     \
    } while (0)

    PFLOAD(0);
    STSW(0);
    PFLOAD(1);
    __syncwarp();
    for (int g = 0; g < NWIN; g++) {
        const int buf = g & 1;
        if (g < NWIN - 4) CONS(tanha, buf);
        else              CONS(ftanh, buf);
        if (g + 1 < NWIN) {
            STSW((g + 1) & 1);
            if (g + 2 < NWIN) PFLOAD(g + 2);
            __syncwarp();
        }
    }

    if (lane < 30) {
        const int dirOff = bwd ? 9 : 0;
        const int bA = wg * TPW + 2 * tri;
        const int bB = bA + 1;
        float a0, b0, a1, b1, a2, b2;
        unpack2(hP[0], a0, b0); unpack2(hP[1], a1, b1); unpack2(hP[2], a2, b2);
        if (bA < BB) {
            float* d = g_y + bA * 18 + dirOff + 3 * r;
            d[0] = a0; d[1] = a1; d[2] = a2;
        }
        if (bB < BB) {
            float* d = g_y + bB * 18 + dirOff + 3 * r;
            d[0] = b0; d[1] = b1; d[2] = b2;
        }
    }
    #undef PFLOAD
    #undef STSW
    #undef ZXH
    #undef STEP
    #undef CONS
}

// ---------------------------------------------------------------------------
// Stage 2: H2=32 RNN, 25 steps + linear 32->3 (R4/R8 version, precise tanh).
// ---------------------------------------------------------------------------
__global__ __launch_bounds__(256) void rnn2_kernel(
    const float* __restrict__ wih2, const float* __restrict__ whh2,
    const float* __restrict__ bih2, const float* __restrict__ bhh2,
    const float* __restrict__ wout, const float* __restrict__ bout,
    float* __restrict__ out)
{
    __shared__ float swh[1024], swi[576], swo[96];
    __shared__ float hs[8][OUTLEN][32];

    const int tid = threadIdx.x;
    for (int i = tid; i < 1024; i += 256) swh[i] = whh2[i];
    for (int i = tid; i < 576;  i += 256) swi[i] = wih2[i];
    if (tid < 96) swo[tid] = wout[tid];
    __syncthreads();

    const int wIn = tid >> 5;
    const int j   = tid & 31;
    const int b   = blockIdx.x * 8 + wIn;

    float Wh[32];
    {
        const float4* p = reinterpret_cast<const float4*>(&swh[j * 32]);
        #pragma unroll
        for (int c = 0; c < 8; c++) {
            float4 v = p[c];
            Wh[4*c] = v.x; Wh[4*c+1] = v.y; Wh[4*c+2] = v.z; Wh[4*c+3] = v.w;
        }
    }
    float Wi[18];
    {
        const float2* p = reinterpret_cast<const float2*>(&swi[j * 18]);
        #pragma unroll
        for (int c = 0; c < 9; c++) { float2 v = p[c]; Wi[2*c] = v.x; Wi[2*c+1] = v.y; }
    }
    const float bj = bih2[j] + bhh2[j];

    float z = bj;
    {
        const float2* yp = reinterpret_cast<const float2*>(g_y + (size_t)b * 18);
        #pragma unroll
        for (int c = 0; c < 9; c++) {
            float2 v = yp[c];
            z = fmaf(Wi[2*c], v.x, z);
            z = fmaf(Wi[2*c+1], v.y, z);
        }
    }
    float h = ftanh(z);
    hs[wIn][0][j] = h;

    for (int t = 1; t < OUTLEN; t++) {
        __syncwarp();
        const float4* hp = reinterpret_cast<const float4*>(&hs[wIn][t - 1][0]);
        float a0 = bj, a1 = 0.f, a2 = 0.f, a3 = 0.f;
        #pragma unroll
        for (int c = 0; c < 8; c += 4) {
            float4 v0 = hp[c],     v1 = hp[c + 1];
            float4 v2 = hp[c + 2], v3 = hp[c + 3];
            a0 = fmaf(Wh[4*c+0],  v0.x, a0); a0 = fmaf(Wh[4*c+1],  v0.y, a0);
            a1 = fmaf(Wh[4*c+2],  v0.z, a1); a1 = fmaf(Wh[4*c+3],  v0.w, a1);
            a2 = fmaf(Wh[4*c+4],  v1.x, a2); a2 = fmaf(Wh[4*c+5],  v1.y, a2);
            a3 = fmaf(Wh[4*c+6],  v1.z, a3); a3 = fmaf(Wh[4*c+7],  v1.w, a3);
            a0 = fmaf(Wh[4*c+8],  v2.x, a0); a0 = fmaf(Wh[4*c+9],  v2.y, a0);
            a1 = fmaf(Wh[4*c+10], v2.z, a1); a1 = fmaf(Wh[4*c+11], v2.w, a1);
            a2 = fmaf(Wh[4*c+12], v3.x, a2); a2 = fmaf(Wh[4*c+13], v3.y, a2);
            a3 = fmaf(Wh[4*c+14], v3.z, a3); a3 = fmaf(Wh[4*c+15], v3.w, a3);
        }
        h = ftanh((a0 + a1) + (a2 + a3));
        hs[wIn][t][j] = h;
    }
    __syncwarp();

    float* op = out + (size_t)b * (OUTLEN * 3);
    for (int p = j; p < OUTLEN * 3; p += 32) {
        const int t = p / 3, o = p - 3 * t;
        const float4* yr = reinterpret_cast<const float4*>(&hs[wIn][t][0]);
        const float4* wr = reinterpret_cast<const float4*>(&swo[o * 32]);
        float acc = bout[o];
        #pragma unroll
        for (int c = 0; c < 8; c++) {
            float4 yv = yr[c], wv = wr[c];
            acc = fmaf(yv.x, wv.x, acc);
            acc = fmaf(yv.y, wv.y, acc);
            acc = fmaf(yv.z, wv.z, acc);
            acc = fmaf(yv.w, wv.w, acc);
        }
        op[p] = acc;
    }
}

// ---------------------------------------------------------------------------
// Launch pattern [rnn1, rnn2, dummy] kept: ncu capture stays on rnn1.
// ---------------------------------------------------------------------------
extern "C" void kernel_launch(void* const* d_in, const int* in_sizes, int n_in,
                              void* d_out, int out_size)
{
    const float* x     = (const float*)d_in[0];
    const float* wih_f = (const float*)d_in[1];
    const float* whh_f = (const float*)d_in[2];
    const float* bih_f = (const float*)d_in[3];
    const float* bhh_f = (const float*)d_in[4];
    const float* wih_b = (const float*)d_in[5];
    const float* whh_b = (const float*)d_in[6];
    const float* bih_b = (const float*)d_in[7];
    const float* bhh_b = (const float*)d_in[8];
    const float* wih2  = (const float*)d_in[9];
    const float* whh2  = (const float*)d_in[10];
    const float* bih2  = (const float*)d_in[11];
    const float* bhh2  = (const float*)d_in[12];
    const float* wout  = (const float*)d_in[13];
    const float* bout  = (const float*)d_in[14];
    float* out = (float*)d_out;

    // 103 CTAs x 4 warps = 412 warps (410 active), 1 CTA/SM, 1 warp/SMSP
    rnn1_kernel<<<103, 128>>>(x, wih_f, whh_f, bih_f, bhh_f,
                              wih_b, whh_b, bih_b, bhh_b);
    rnn2_kernel<<<512, 256>>>(wih2, whh2, bih2, bhh2, wout, bout, out);
    dummy_kernel<<<1, 32>>>();
}

// round 10
// speedup vs baseline: 1.0792x; 1.0792x over previous
#include <cuda_runtime.h>
typedef unsigned long long u64;

#define TT 2048
#define BB 4096
#define OUTLEN 25
#define TPW 20             // batches per warp: 10 pairs x 2 packed
#define WPD 205            // warps per direction
#define NWIN (TT/8)        // 256 windows of 8 steps
#define PSTRIDE 50         // u64 stride per pair in smem (400B: 16B-aligned,
                           // banks shift 4 words/pair -> near-conflict-free)

__device__ float g_y[BB * 18];

__device__ __forceinline__ u64 pack2(float lo, float hi) {
    u64 d; asm("mov.b64 %0,{%1,%2};" : "=l"(d) : "f"(lo), "f"(hi)); return d;
}
__device__ __forceinline__ void unpack2(u64 v, float& lo, float& hi) {
    asm("mov.b64 {%0,%1},%2;" : "=f"(lo), "=f"(hi) : "l"(v));
}
__device__ __forceinline__ u64 fma2(u64 a, u64 b, u64 c) {
    u64 d; asm("fma.rn.f32x2 %0,%1,%2,%3;" : "=l"(d) : "l"(a), "l"(b), "l"(c)); return d;
}
__device__ __forceinline__ u64 mul2(u64 a, u64 b) {
    u64 d; asm("mul.rn.f32x2 %0,%1,%2;" : "=l"(d) : "l"(a), "l"(b)); return d;
}
__device__ __forceinline__ u64 add2(u64 a, u64 b) {
    u64 d; asm("add.rn.f32x2 %0,%1,%2;" : "=l"(d) : "l"(a), "l"(b)); return d;
}
__device__ __forceinline__ float tanha(float x) {
    float y; asm("tanh.approx.f32 %0,%1;" : "=f"(y) : "f"(x)); return y;
}
__device__ __forceinline__ float ftanh(float x) {
    x = fminf(fmaxf(x, -9.0f), 9.0f);
    float e = __expf(2.0f * x);
    return __fdividef(e - 1.0f, e + 1.0f);
}

__global__ void dummy_kernel() {}

// ---------------------------------------------------------------------------
// Stage 1: bidirectional Elman RNN H1=9 over T=2048, f32x2-packed.
// Warp = 10 lane-triples x 2 batches (lo/hi of f32x2). Lane r of a triple
// owns units 3r..3r+2 of both batches. 103 CTAs x 4 warps = 1 warp/SMSP.
// x PRE-PACKED by the loader into per-warp smem as (A,B) u64s, layout
// [pair*PSTRIDE + q*6 + k] (PSTRIDE=50 -> 16B-aligned vectors, banks shift
// 4 words/pair; R9's stride-48 all-pairs-same-bank bug fixed).
// Consumer: 2xLDS.128 + LDS.64 per step, zero pack instructions.
// STEP is the R8-measured form: zx+own-h 3-chain, Ha/Bb trees parallel.
// tanh.approx except the last 32 steps (precise tail; contraction wipes the
// approx error - rel_err pinned at 1.7e-7 across R0/R5/R6/R8/R9).
// ---------------------------------------------------------------------------
__global__ __launch_bounds__(128, 1) void rnn1_kernel(
    const float* __restrict__ x,
    const float* __restrict__ wih_f, const float* __restrict__ whh_f,
    const float* __restrict__ bih_f, const float* __restrict__ bhh_f,
    const float* __restrict__ wih_b, const float* __restrict__ whh_b,
    const float* __restrict__ bih_b, const float* __restrict__ bhh_b)
{
    __shared__ u64 sxu[4][2][10 * PSTRIDE];

    const int wIn  = threadIdx.x >> 5;
    const int lane = threadIdx.x & 31;
    const int wid  = blockIdx.x * 4 + wIn;
    if (wid >= 2 * WPD) return;

    const bool bwd = (wid >= WPD);
    const int  wg  = bwd ? wid - WPD : wid;
    const int  tri = min(lane / 3, 9);     // lanes 30,31 shadow pair 9
    const int  r   = lane % 3;
    const int  rA  = (r + 1) % 3, rB = (r + 2) % 3;
    const int  laneA = 3 * tri + rA, laneB = 3 * tri + rB;

    const float* wih = bwd ? wih_b : wih_f;
    const float* whh = bwd ? whh_b : whh_f;
    const float* bih = bwd ? bih_b : bih_f;
    const float* bhh = bwd ? bhh_b : bhh_f;

    // packed weights (same value both halves; both batches share direction)
    u64 WX[3][5], WhO[3][3], WhA[3][3], WhB[3][3], B2[3];
    #pragma unroll
    for (int m = 0; m < 3; m++) {
        const int j = 3 * r + m;
        #pragma unroll
        for (int k = 0; k < 5; k++) { float w = wih[j*5+k]; WX[m][k] = pack2(w, w); }
        #pragma unroll
        for (int i = 0; i < 3; i++) {
            float wo = whh[j*9 + 3*r  + i]; WhO[m][i] = pack2(wo, wo);
            float wa = whh[j*9 + 3*rA + i]; WhA[m][i] = pack2(wa, wa);
            float wb = whh[j*9 + 3*rB + i]; WhB[m][i] = pack2(wb, wb);
        }
        float bv = bih[j] + bhh[j];
        B2[m] = pack2(bv, bv);
    }

    // ---- loader: 100 chunks (pair p 0..9, chunk c 0..9). Chunk c = float4
    // covering window-flat floats 4c..4c+3 (flat = q*5+k). Lane handles
    // chunks lane, lane+32, lane+64 (+96 for lanes 0..3): LDG.128 from
    // batch 2p (A) and 2p+1 (B), packs 4 u64s, STS.64 to [p*50 + q*6 + k].
    const char* xc = (const char*)x;
    size_t   gA[4], gB[4];
    unsigned dstix[4][4];
    #pragma unroll
    for (int kk = 0; kk < 4; kk++) {
        int idc = min(lane + 32 * kk, 99);
        int p = idc / 10, c = idc - 10 * p;
        int ba = min(wg * TPW + 2 * p, BB - 1);
        int bb = min(ba + 1, BB - 1);
        gA[kk] = (size_t)ba * (TT * 20) + (size_t)c * 16;
        gB[kk] = (size_t)bb * (TT * 20) + (size_t)c * 16;
        #pragma unroll
        for (int u = 0; u < 4; u++) {
            int flat = 4 * c + u;
            int q = flat / 5, k = flat - 5 * q;
            dstix[kk][u] = (unsigned)(p * PSTRIDE + q * 6 + k);
        }
    }
    float4 pfA[4], pfB[4];

    #define PFLOAD(g) do {                                                    \
        size_t wb = (size_t)(bwd ? (TT - 8 - 8 * (g)) : (8 * (g))) * 20;      \
        _Pragma("unroll")                                                     \
        for (int kk = 0; kk < 4; kk++)                                        \
            if (lane + 32 * kk < 100) {                                       \
                pfA[kk] = *reinterpret_cast<const float4*>(xc + gA[kk] + wb); \
                pfB[kk] = *reinterpret_cast<const float4*>(xc + gB[kk] + wb); \
            }                                                                 \
    } while (0)

    #define STSW(buf) do {                                                    \
        u64* s = &sxu[wIn][buf][0];                                           \
        _Pragma("unroll")                                                     \
        for (int kk = 0; kk < 4; kk++)                                        \
            if (lane + 32 * kk < 100) {                                       \
                s[dstix[kk][0]] = pack2(pfA[kk].x, pfB[kk].x);                \
                s[dstix[kk][1]] = pack2(pfA[kk].y, pfB[kk].y);                \
                s[dstix[kk][2]] = pack2(pfA[kk].z, pfB[kk].z);                \
                s[dstix[kk][3]] = pack2(pfA[kk].w, pfB[kk].w);                \
            }                                                                 \
    } while (0)

    u64 hP[3] = {0, 0, 0}, Ha[3] = {0, 0, 0}, Hb[3] = {0, 0, 0};
    u64 zxw[4][3];

    // bulk x-projection for a 4-step half-window: pre-packed u64 reads,
    // no pack instructions; 16B-aligned vector loads.
    #define ZXH(buf, half) do {                                               \
        const u64* xs = &sxu[wIn][buf][tri * PSTRIDE + (half) * 24];          \
        _Pragma("unroll")                                                     \
        for (int q = 0; q < 4; q++) {                                         \
            ulonglong2 v01 = *reinterpret_cast<const ulonglong2*>(xs + q*6);  \
            ulonglong2 v23 = *reinterpret_cast<const ulonglong2*>(xs + q*6+2);\
            u64 X4 = xs[q*6+4];                                               \
            _Pragma("unroll")                                                 \
            for (int m = 0; m < 3; m++) {                                     \
                u64 z = fma2(WX[m][0], v01.x, B2[m]);                         \
                z = fma2(WX[m][1], v01.y, z); z = fma2(WX[m][2], v23.x, z);   \
                z = fma2(WX[m][3], v23.y, z); z = fma2(WX[m][4], X4, z);      \
                zxw[q][m] = z;                                                \
            }                                                                 \
        }                                                                     \
    } while (0)

    // recurrent step, R8 form: own-h chain seeds from zx (issues in the shfl
    // shadow), Ha/Hb trees parallel, two-level add merge.
    #define STEP(TANHF, q) do {                                               \
        u64 nh[3];                                                            \
        _Pragma("unroll")                                                     \
        for (int m = 0; m < 3; m++) {                                         \
            u64 t1 = fma2(WhO[m][2], hP[2], zxw[q][m]);                       \
            t1 = fma2(WhO[m][1], hP[1], t1);                                  \
            t1 = fma2(WhO[m][0], hP[0], t1);                                  \
            u64 t2 = mul2(WhA[m][0], Ha[0]);                                  \
            t2 = fma2(WhA[m][1], Ha[1], t2); t2 = fma2(WhA[m][2], Ha[2], t2); \
            u64 t3 = mul2(WhB[m][0], Hb[0]);                                  \
            t3 = fma2(WhB[m][1], Hb[1], t3); t3 = fma2(WhB[m][2], Hb[2], t3); \
            u64 z = add2(add2(t1, t2), t3);                                   \
            float sa, sb; unpack2(z, sa, sb);                                 \
            nh[m] = pack2(TANHF(sa), TANHF(sb));                              \
        }                                                                     \
        hP[0] = nh[0]; hP[1] = nh[1]; hP[2] = nh[2];                          \
        Ha[0] = __shfl_sync(0xffffffffu, hP[0], laneA);                       \
        Ha[1] = __shfl_sync(0xffffffffu, hP[1], laneA);                       \
        Ha[2] = __shfl_sync(0xffffffffu, hP[2], laneA);                       \
        Hb[0] = __shfl_sync(0xffffffffu, hP[0], laneB);                       \
        Hb[1] = __shfl_sync(0xffffffffu, hP[1], laneB);                       \
        Hb[2] = __shfl_sync(0xffffffffu, hP[2], laneB);                       \
    } while (0)

    #define CONS(TANHF, buf) do {                                             \
        if (!bwd) {                                                           \
            ZXH(buf, 0);                                                      \
            STEP(TANHF, 0); STEP(TANHF, 1); STEP(TANHF, 2); STEP(TANHF, 3);   \
            ZXH(buf, 1);                                                      \
            STEP(TANHF, 0); STEP(TANHF, 1); STEP(TANHF, 2); STEP(TANHF, 3);   \
        } else {                                                              \
            ZXH(buf, 1);                                                      \
            STEP(TANHF, 3); STEP(TANHF, 2); STEP(TANHF, 1); STEP(TANHF, 0);   \
            ZXH(buf, 0);                                                      \
            STEP(TANHF, 3); STEP(TANHF, 2); STEP(TANHF, 1); STEP(TANHF, 0);   \
        }                                                                     \
    } while (0)

    PFLOAD(0);
    STSW(0);
    PFLOAD(1);
    __syncwarp();
    for (int g = 0; g < NWIN; g++) {
        const int buf = g & 1;
        if (g < NWIN - 4) CONS(tanha, buf);
        else              CONS(ftanh, buf);
        if (g + 1 < NWIN) {
            STSW((g + 1) & 1);
            if (g + 2 < NWIN) PFLOAD(g + 2);
            __syncwarp();
        }
    }

    if (lane < 30) {
        const int dirOff = bwd ? 9 : 0;
        const int bA = wg * TPW + 2 * tri;
        const int bB = bA + 1;
        float a0, b0, a1, b1, a2, b2;
        unpack2(hP[0], a0, b0); unpack2(hP[1], a1, b1); unpack2(hP[2], a2, b2);
        if (bA < BB) {
            float* d = g_y + bA * 18 + dirOff + 3 * r;
            d[0] = a0; d[1] = a1; d[2] = a2;
        }
        if (bB < BB) {
            float* d = g_y + bB * 18 + dirOff + 3 * r;
            d[0] = b0; d[1] = b1; d[2] = b2;
        }
    }
    #undef PFLOAD
    #undef STSW
    #undef ZXH
    #undef STEP
    #undef CONS
}

// ---------------------------------------------------------------------------
// Stage 2: H2=32 RNN, 25 steps + linear 32->3 (R4/R8 version, precise tanh).
// ---------------------------------------------------------------------------
__global__ __launch_bounds__(256) void rnn2_kernel(
    const float* __restrict__ wih2, const float* __restrict__ whh2,
    const float* __restrict__ bih2, const float* __restrict__ bhh2,
    const float* __restrict__ wout, const float* __restrict__ bout,
    float* __restrict__ out)
{
    __shared__ float swh[1024], swi[576], swo[96];
    __shared__ float hs[8][OUTLEN][32];

    const int tid = threadIdx.x;
    for (int i = tid; i < 1024; i += 256) swh[i] = whh2[i];
    for (int i = tid; i < 576;  i += 256) swi[i] = wih2[i];
    if (tid < 96) swo[tid] = wout[tid];
    __syncthreads();

    const int wIn = tid >> 5;
    const int j   = tid & 31;
    const int b   = blockIdx.x * 8 + wIn;

    float Wh[32];
    {
        const float4* p = reinterpret_cast<const float4*>(&swh[j * 32]);
        #pragma unroll
        for (int c = 0; c < 8; c++) {
            float4 v = p[c];
            Wh[4*c] = v.x; Wh[4*c+1] = v.y; Wh[4*c+2] = v.z; Wh[4*c+3] = v.w;
        }
    }
    float Wi[18];
    {
        const float2* p = reinterpret_cast<const float2*>(&swi[j * 18]);
        #pragma unroll
        for (int c = 0; c < 9; c++) { float2 v = p[c]; Wi[2*c] = v.x; Wi[2*c+1] = v.y; }
    }
    const float bj = bih2[j] + bhh2[j];

    float z = bj;
    {
        const float2* yp = reinterpret_cast<const float2*>(g_y + (size_t)b * 18);
        #pragma unroll
        for (int c = 0; c < 9; c++) {
            float2 v = yp[c];
            z = fmaf(Wi[2*c], v.x, z);
            z = fmaf(Wi[2*c+1], v.y, z);
        }
    }
    float h = ftanh(z);
    hs[wIn][0][j] = h;

    for (int t = 1; t < OUTLEN; t++) {
        __syncwarp();
        const float4* hp = reinterpret_cast<const float4*>(&hs[wIn][t - 1][0]);
        float a0 = bj, a1 = 0.f, a2 = 0.f, a3 = 0.f;
        #pragma unroll
        for (int c = 0; c < 8; c += 4) {
            float4 v0 = hp[c],     v1 = hp[c + 1];
            float4 v2 = hp[c + 2], v3 = hp[c + 3];
            a0 = fmaf(Wh[4*c+0],  v0.x, a0); a0 = fmaf(Wh[4*c+1],  v0.y, a0);
            a1 = fmaf(Wh[4*c+2],  v0.z, a1); a1 = fmaf(Wh[4*c+3],  v0.w, a1);
            a2 = fmaf(Wh[4*c+4],  v1.x, a2); a2 = fmaf(Wh[4*c+5],  v1.y, a2);
            a3 = fmaf(Wh[4*c+6],  v1.z, a3); a3 = fmaf(Wh[4*c+7],  v1.w, a3);
            a0 = fmaf(Wh[4*c+8],  v2.x, a0); a0 = fmaf(Wh[4*c+9],  v2.y, a0);
            a1 = fmaf(Wh[4*c+10], v2.z, a1); a1 = fmaf(Wh[4*c+11], v2.w, a1);
            a2 = fmaf(Wh[4*c+12], v3.x, a2); a2 = fmaf(Wh[4*c+13], v3.y, a2);
            a3 = fmaf(Wh[4*c+14], v3.z, a3); a3 = fmaf(Wh[4*c+15], v3.w, a3);
        }
        h = ftanh((a0 + a1) + (a2 + a3));
        hs[wIn][t][j] = h;
    }
    __syncwarp();

    float* op = out + (size_t)b * (OUTLEN * 3);
    for (int p = j; p < OUTLEN * 3; p += 32) {
        const int t = p / 3, o = p - 3 * t;
        const float4* yr = reinterpret_cast<const float4*>(&hs[wIn][t][0]);
        const float4* wr = reinterpret_cast<const float4*>(&swo[o * 32]);
        float acc = bout[o];
        #pragma unroll
        for (int c = 0; c < 8; c++) {
            float4 yv = yr[c], wv = wr[c];
            acc = fmaf(yv.x, wv.x, acc);
            acc = fmaf(yv.y, wv.y, acc);
            acc = fmaf(yv.z, wv.z, acc);
            acc = fmaf(yv.w, wv.w, acc);
        }
        op[p] = acc;
    }
}

// ---------------------------------------------------------------------------
// Launch pattern [rnn1, rnn2, dummy] kept: ncu capture stays on rnn1.
// ---------------------------------------------------------------------------
extern "C" void kernel_launch(void* const* d_in, const int* in_sizes, int n_in,
                              void* d_out, int out_size)
{
    const float* x     = (const float*)d_in[0];
    const float* wih_f = (const float*)d_in[1];
    const float* whh_f = (const float*)d_in[2];
    const float* bih_f = (const float*)d_in[3];
    const float* bhh_f = (const float*)d_in[4];
    const float* wih_b = (const float*)d_in[5];
    const float* whh_b = (const float*)d_in[6];
    const float* bih_b = (const float*)d_in[7];
    const float* bhh_b = (const float*)d_in[8];
    const float* wih2  = (const float*)d_in[9];
    const float* whh2  = (const float*)d_in[10];
    const float* bih2  = (const float*)d_in[11];
    const float* bhh2  = (const float*)d_in[12];
    const float* wout  = (const float*)d_in[13];
    const float* bout  = (const float*)d_in[14];
    float* out = (float*)d_out;

    // 103 CTAs x 4 warps = 412 warps (410 active), 1 CTA/SM, 1 warp/SMSP
    rnn1_kernel<<<103, 128>>>(x, wih_f, whh_f, bih_f, bhh_f,
                              wih_b, whh_b, bih_b, bhh_b);
    rnn2_kernel<<<512, 256>>>(wih2, whh2, bih2, bhh2, wout, bout, out);
    dummy_kernel<<<1, 32>>>();
}